// round 10
// baseline (speedup 1.0000x reference)
#include <cuda_runtime.h>
#include <cuda_pipeline.h>
#include <cstdint>

#define BB 4
#define CC 64
#define HH 128
#define WW 416
#define HW (HH*WW)
#define CHW (CC*HH*WW)

// Scratch for warped x2 (no cudaMalloc allowed)
__device__ float g_x2w[(size_t)BB*CHW];

__device__ __forceinline__ float lrelu(float v) { return v >= 0.f ? v : 0.1f*v; }

__device__ __forceinline__ uint32_t f2tf32(float f) {
    uint32_t u; asm("cvt.rna.tf32.f32 %0, %1;" : "=r"(u) : "f"(f)); return u;
}

__device__ __forceinline__ void mma_tf32(float* c, const uint32_t* a,
                                         uint32_t b0, uint32_t b1) {
    asm volatile(
        "mma.sync.aligned.m16n8k8.row.col.f32.tf32.tf32.f32 "
        "{%0,%1,%2,%3}, {%4,%5,%6,%7}, {%8,%9}, {%0,%1,%2,%3};"
        : "+f"(c[0]), "+f"(c[1]), "+f"(c[2]), "+f"(c[3])
        : "r"(a[0]), "r"(a[1]), "r"(a[2]), "r"(a[3]), "r"(b0), "r"(b1));
}

// ===========================================================================
// Fused kernel: blocks x=0..3 = tf32 mma.sync banded disparity GEMM (M=128)
//               block  x=4    = bilinear warp of one full row (filler)
// A[m][k] = x1[k][x0+m];  B[n][k] = r1[k][x0-96+n] (zero-padded), n=0..319.
// D[m][n] = sum_k A*B;  out[d][x0+m] = lrelu(D[m][m+d]), d=0..191.
// ===========================================================================
#define SKA 132                      // s_a row stride (floats)
#define SKB 328                      // s_b row stride
#define SKO 132                      // s_out row stride
#define SA_OFF 0
#define SB_OFF (64*SKA)              // 8448
#define SO_OFF (SB_OFF + 64*SKB)     // 29440
#define SM_FLOATS (SO_OFF + 192*SKO) // 54784
#define SM_TOTAL (SM_FLOATS*4)       // 219136 B

__global__ void __launch_bounds__(256, 1)
disp_mma_warp(const float* __restrict__ x1, const float* __restrict__ r1,
              const float* __restrict__ x2, const float* __restrict__ flow,
              float* __restrict__ out) {
    extern __shared__ float sm[];
    const int y = blockIdx.y, b = blockIdx.z;
    const int t = threadIdx.x;

    if (blockIdx.x == 4) {
        // ------------------ warp path: whole row y of batch b ---------------
        float* s_w = sm;                  // [4][WW]
        int*   s_i = (int*)(sm + 4*WW);   // [4][WW]
        for (int xi = t; xi < WW; xi += 256) {
            const float fx = flow[((size_t)(b*2+0)*HH + y)*WW + xi];
            const float fy = flow[((size_t)(b*2+1)*HH + y)*WW + xi];
            const float gx = (float)xi + fx;
            const float gy = (float)y + fy;
            const float x0f = floorf(gx), y0f = floorf(gy);
            const float wx = gx - x0f, wy = gy - y0f;
            const int x0 = (int)x0f, y0 = (int)y0f;
            const int x1i = x0 + 1,  y1i = y0 + 1;
            const float vx0 = (x0  >= 0 && x0  < WW) ? 1.f : 0.f;
            const float vx1 = (x1i >= 0 && x1i < WW) ? 1.f : 0.f;
            const float vy0 = (y0  >= 0 && y0  < HH) ? 1.f : 0.f;
            const float vy1 = (y1i >= 0 && y1i < HH) ? 1.f : 0.f;
            const int x0c = min(max(x0, 0), WW-1);
            const int x1c = min(max(x1i,0), WW-1);
            const int y0c = min(max(y0, 0), HH-1);
            const int y1c = min(max(y1i,0), HH-1);
            s_w[0*WW+xi] = (1.f-wx)*(1.f-wy)*vx0*vy0;
            s_w[1*WW+xi] = wx*(1.f-wy)*vx1*vy0;
            s_w[2*WW+xi] = (1.f-wx)*wy*vx0*vy1;
            s_w[3*WW+xi] = wx*wy*vx1*vy1;
            s_i[0*WW+xi] = y0c*WW + x0c;
            s_i[1*WW+xi] = y0c*WW + x1c;
            s_i[2*WW+xi] = y1c*WW + x0c;
            s_i[3*WW+xi] = y1c*WW + x1c;
        }
        __syncthreads();

        const float* xb = x2 + (size_t)b*CHW;
        float* ob = g_x2w + (size_t)b*CHW + (size_t)y*WW;
#pragma unroll 2
        for (int c = 0; c < CC; c++) {
            const float* p = xb + (size_t)c*HW;
            float* o = ob + (size_t)c*HW;
            for (int xi = t; xi < WW; xi += 256) {
                o[xi] = s_w[0*WW+xi]*__ldg(p+s_i[0*WW+xi])
                      + s_w[1*WW+xi]*__ldg(p+s_i[1*WW+xi])
                      + s_w[2*WW+xi]*__ldg(p+s_i[2*WW+xi])
                      + s_w[3*WW+xi]*__ldg(p+s_i[3*WW+xi]);
            }
        }
        return;
    }

    // ------------------ tensor-core disparity path ------------------
    const int x0t = (blockIdx.x < 3) ? blockIdx.x * 128 : 288;
    uint32_t* s_a = (uint32_t*)sm;              // [64][SKA]  A: k-major rows
    uint32_t* s_b = (uint32_t*)(sm + SB_OFF);   // [64][SKB]  B: k rows, n cols
    float*    s_o = sm + SO_OFF;                // [192][SKO] band output

    // ---- fill A: s_a[k][m] = tf32(x1[k][x0t+m]), m=0..127 ----
    {
        const float* ap = x1 + (size_t)b*CHW + (size_t)y*WW + x0t;
        for (int g = t; g < 64*32; g += 256) {
            const int k = g >> 5, mq = (g & 31) << 2;
            const float4 v = *(const float4*)(ap + (size_t)k*HW + mq);
            uint4 u;
            u.x = f2tf32(v.x); u.y = f2tf32(v.y);
            u.z = f2tf32(v.z); u.w = f2tf32(v.w);
            *(uint4*)(s_a + k*SKA + mq) = u;
        }
    }
    // ---- fill B: s_b[k][n] = tf32(r1[k][x0t-96+n]), n=0..319, zero-pad ----
    {
        const float* rp = r1 + (size_t)b*CHW + (size_t)y*WW;
        for (int g = t; g < 64*80; g += 256) {
            const int k = g / 80, nq = (g - 80*k) << 2;
            const int x = x0t - 96 + nq;
            uint4 u = make_uint4(0u, 0u, 0u, 0u);
            if ((unsigned)x < WW) {
                const float4 v = *(const float4*)(rp + (size_t)k*HW + x);
                u.x = f2tf32(v.x); u.y = f2tf32(v.y);
                u.z = f2tf32(v.z); u.w = f2tf32(v.w);
            }
            *(uint4*)(s_b + k*SKB + nq) = u;
        }
    }
    __syncthreads();

    // ---- per-warp banded GEMM: warp w owns m-tile [16w, 16w+16) ----
    const int w = t >> 5, lane = t & 31;
    const int gid = lane >> 2, tig = lane & 3;
    const int m0w = w << 4;

    // preload A fragments for all 8 k-steps (32 regs)
    uint32_t afr[8][4];
#pragma unroll
    for (int kt = 0; kt < 8; kt++) {
        const int k0 = kt * 8;
        afr[kt][0] = s_a[(k0 + tig)    *SKA + m0w + gid];
        afr[kt][1] = s_a[(k0 + tig)    *SKA + m0w + gid + 8];
        afr[kt][2] = s_a[(k0 + tig + 4)*SKA + m0w + gid];
        afr[kt][3] = s_a[(k0 + tig + 4)*SKA + m0w + gid + 8];
    }

    const int mA = m0w + gid, mB = mA + 8;
    for (int nt = 0; nt < 26; nt++) {
        const int n0 = m0w + nt*8;
        float ce[4] = {0.f, 0.f, 0.f, 0.f};
        float co[4] = {0.f, 0.f, 0.f, 0.f};
#pragma unroll
        for (int kt = 0; kt < 8; kt += 2) {
            {
                const int k0 = kt * 8;
                const uint32_t b0 = s_b[(k0 + tig)    *SKB + n0 + gid];
                const uint32_t b1 = s_b[(k0 + tig + 4)*SKB + n0 + gid];
                mma_tf32(ce, afr[kt], b0, b1);
            }
            {
                const int k0 = (kt + 1) * 8;
                const uint32_t b0 = s_b[(k0 + tig)    *SKB + n0 + gid];
                const uint32_t b1 = s_b[(k0 + tig + 4)*SKB + n0 + gid];
                mma_tf32(co, afr[kt + 1], b0, b1);
            }
        }
        // band extraction: D[m][n] -> s_o[n-m][m]
        const int d0 = nt*8 + 2*tig - gid;     // for rows gid (c0/c1)
        const int d2 = d0 - 8;                 // for rows gid+8 (c2/c3)
        if ((unsigned)d0       < 192u) s_o[d0*SKO + mA]     = lrelu(ce[0] + co[0]);
        if ((unsigned)(d0 + 1) < 192u) s_o[(d0+1)*SKO + mA] = lrelu(ce[1] + co[1]);
        if ((unsigned)d2       < 192u) s_o[d2*SKO + mB]     = lrelu(ce[2] + co[2]);
        if ((unsigned)(d2 + 1) < 192u) s_o[(d2+1)*SKO + mB] = lrelu(ce[3] + co[3]);
    }
    __syncthreads();

    // ---- coalesced store: 192 d-rows x 128 x ----
    {
        float* op = out + ((size_t)(b*273 + 81)*HH + y)*WW + x0t;
        for (int i = t; i < 192*32; i += 256) {
            const int d = i >> 5, q = (i & 31) << 2;
            const float4 v = *(const float4*)(s_o + d*SKO + q);
            *(float4*)(op + (size_t)d*HW + q) = v;
        }
    }
}

// ===========================================================================
// 81-channel cost volume  out[b, dy*9+dx, y, x] =
//   lrelu( sum_c x1[b,c,y,x] * x2w[b,c,y+dy-4,x+dx-4] ),  zero padded.
// (unchanged: FFMA + cp.async double buffer, 3 blocks/SM)
// ===========================================================================
#define TXC 104
#define CTC 8
#define BWC 112
#define NTC (CC/CTC)
#define CORR_BUF (CTC*TXC + 9*CTC*BWC)
#define CORR_SMEM (2*CORR_BUF*4)

__global__ __launch_bounds__(256, 3)
void corr_kernel(const float* __restrict__ x1, float* __restrict__ out) {
    extern __shared__ float sm[];

    const int x0t = blockIdx.x * TXC;
    const int y = blockIdx.y, b = blockIdx.z;
    const int t = threadIdx.x;
    const int dy = t / 26;
    const int xg = t - dy*26;
    const bool act = (t < 234);

    const float* x1p = x1 + (size_t)b*CHW + (size_t)y*WW + x0t;
    const float* wp  = g_x2w + (size_t)b*CHW;

    const int ca = t / 26, xa = (t - 26*ca) * 4;
    const int cb = t / 28, xb4 = (t - 28*cb) * 4;
    const int gx2 = x0t - 4 + xb4;
    const bool px = ((unsigned)gx2 < WW);

    float acc[9][4];
#pragma unroll
    for (int i = 0; i < 9; i++)
#pragma unroll
        for (int j = 0; j < 4; j++) acc[i][j] = 0.f;

    auto load_tile = [&](int bi, int kt) {
        float* da = sm + bi*CORR_BUF;
        float* db = da + CTC*TXC;
        const int ct = kt * CTC;
        if (t < 208)
            __pipeline_memcpy_async(da + ca*TXC + xa,
                                    x1p + (size_t)(ct+ca)*HW + xa, 16);
        if (t < 224) {
            const float* srcb = wp + (size_t)(ct+cb)*HW + gx2;
            float* dstb = db + cb*BWC + xb4;
#pragma unroll
            for (int r = 0; r < 9; r++) {
                const int gy2 = y + r - 4;
                if (px && (unsigned)gy2 < HH)
                    __pipeline_memcpy_async(dstb + r*(CTC*BWC), srcb + gy2*WW, 16);
                else
                    *reinterpret_cast<float4*>(dstb + r*(CTC*BWC)) =
                        make_float4(0.f,0.f,0.f,0.f);
            }
        }
    };

    load_tile(0, 0);
    __pipeline_commit();

    for (int k = 0; k < NTC; k++) {
        if (k + 1 < NTC) {
            load_tile((k+1) & 1, k+1);
            __pipeline_commit();
            __pipeline_wait_prior(1);
        } else {
            __pipeline_wait_prior(0);
        }
        __syncthreads();

        if (act) {
            const float* da = sm + (k&1)*CORR_BUF;
            const float* ap = da + xg*4;
            const float* bp = da + CTC*TXC + dy*(CTC*BWC) + xg*4;
#pragma unroll
            for (int c = 0; c < CTC; c++) {
                const float4 a  = *reinterpret_cast<const float4*>(ap + c*TXC);
                const float4 q0 = *reinterpret_cast<const float4*>(bp + c*BWC);
                const float4 q1 = *reinterpret_cast<const float4*>(bp + c*BWC + 4);
                const float4 q2 = *reinterpret_cast<const float4*>(bp + c*BWC + 8);
                const float bv[12] = {q0.x,q0.y,q0.z,q0.w, q1.x,q1.y,q1.z,q1.w,
                                      q2.x,q2.y,q2.z,q2.w};
#pragma unroll
                for (int dx = 0; dx < 9; dx++) {
                    acc[dx][0] += a.x*bv[dx+0];
                    acc[dx][1] += a.y*bv[dx+1];
                    acc[dx][2] += a.z*bv[dx+2];
                    acc[dx][3] += a.w*bv[dx+3];
                }
            }
        }
        __syncthreads();
    }

    if (act) {
        float* op = out + ((size_t)(b*273 + dy*9)*HH + y)*WW + x0t + xg*4;
#pragma unroll
        for (int dx = 0; dx < 9; dx++) {
            float4 v;
            v.x = lrelu(acc[dx][0]);
            v.y = lrelu(acc[dx][1]);
            v.z = lrelu(acc[dx][2]);
            v.w = lrelu(acc[dx][3]);
            *reinterpret_cast<float4*>(op + (size_t)dx*HW) = v;
        }
    }
}

// ===========================================================================
extern "C" void kernel_launch(void* const* d_in, const int* in_sizes, int n_in,
                              void* d_out, int out_size) {
    const float* x1   = (const float*)d_in[0];
    const float* x2   = (const float*)d_in[1];
    const float* r1   = (const float*)d_in[2];
    const float* flow = (const float*)d_in[3];
    float* out = (float*)d_out;

    cudaFuncSetAttribute(disp_mma_warp,
                         cudaFuncAttributeMaxDynamicSharedMemorySize, SM_TOTAL);
    cudaFuncSetAttribute(corr_kernel,
                         cudaFuncAttributeMaxDynamicSharedMemorySize, CORR_SMEM);

    disp_mma_warp<<<dim3(5, HH, BB), 256, SM_TOTAL>>>(x1, r1, x2, flow, out);
    corr_kernel<<<dim3(WW/TXC, HH, BB), 256, CORR_SMEM>>>(x1, out);
}

// round 11
// speedup vs baseline: 1.8451x; 1.8451x over previous
#include <cuda_runtime.h>
#include <cuda_pipeline.h>

#define BB 4
#define CC 64
#define HH 128
#define WW 416
#define HW (HH*WW)
#define CHW (CC*HH*WW)

// Scratch for warped x2 (no cudaMalloc allowed)
__device__ float g_x2w[(size_t)BB*CHW];

__device__ __forceinline__ float lrelu(float v) { return v >= 0.f ? v : 0.1f*v; }

// ===========================================================================
// Fused kernel: blocks 0..3 in x = 192-ch disparity cost volume (FMA-bound)
//               blocks 4..7 in x = bilinear warp of x2 (latency-bound filler)
// 16d x 4x per thread; __launch_bounds__(320,2) -> 2 resident blocks/SM.
// ===========================================================================
#define TXD 104
#define RWD 296                         // 104 + 191 halo, padded to mult of 4
#define CTD 16
#define NTD (CC/CTD)                    // 4 pipeline stages
#define DISP_BUF (CTD*TXD + CTD*RWD)    // 6400 floats per buffer
#define DSP_SMEM (2*DISP_BUF*4)         // 51200 B

__global__ __launch_bounds__(320, 2)
void fused_disp_warp(const float* __restrict__ x1, const float* __restrict__ r1,
                     const float* __restrict__ x2, const float* __restrict__ flow,
                     float* __restrict__ out) {
    extern __shared__ float sm[];
    const int y = blockIdx.y, b = blockIdx.z;
    const int t = threadIdx.x;

    if (blockIdx.x >= 4) {
        // ------------------ warp path ------------------
        const int x0t = (blockIdx.x - 4) * TXD;
        float* s_w = sm;                  // [4][TXD] weights
        int*   s_i = (int*)(sm + 4*TXD);  // [4][TXD] gather indices

        if (t < TXD) {
            const int x = x0t + t;
            const float fx = flow[((size_t)(b*2+0)*HH + y)*WW + x];
            const float fy = flow[((size_t)(b*2+1)*HH + y)*WW + x];
            const float gx = (float)x + fx;
            const float gy = (float)y + fy;
            const float x0f = floorf(gx), y0f = floorf(gy);
            const float wx = gx - x0f, wy = gy - y0f;
            const int x0 = (int)x0f, y0 = (int)y0f;
            const int x1i = x0 + 1,  y1i = y0 + 1;

            const float vx0 = (x0  >= 0 && x0  < WW) ? 1.f : 0.f;
            const float vx1 = (x1i >= 0 && x1i < WW) ? 1.f : 0.f;
            const float vy0 = (y0  >= 0 && y0  < HH) ? 1.f : 0.f;
            const float vy1 = (y1i >= 0 && y1i < HH) ? 1.f : 0.f;

            const int x0c = min(max(x0, 0), WW-1);
            const int x1c = min(max(x1i,0), WW-1);
            const int y0c = min(max(y0, 0), HH-1);
            const int y1c = min(max(y1i,0), HH-1);

            s_w[0*TXD+t] = (1.f-wx)*(1.f-wy)*vx0*vy0;
            s_w[1*TXD+t] = wx*(1.f-wy)*vx1*vy0;
            s_w[2*TXD+t] = (1.f-wx)*wy*vx0*vy1;
            s_w[3*TXD+t] = wx*wy*vx1*vy1;
            s_i[0*TXD+t] = y0c*WW + x0c;
            s_i[1*TXD+t] = y0c*WW + x1c;
            s_i[2*TXD+t] = y1c*WW + x0c;
            s_i[3*TXD+t] = y1c*WW + x1c;
        }
        __syncthreads();

        const float* xb = x2 + (size_t)b*CHW;
        float* ob = g_x2w + (size_t)b*CHW + (size_t)y*WW + x0t;
        for (int e = t; e < TXD*CC; e += 320) {
            const int c = e / TXD, xi = e - c*TXD;
            const float w00 = s_w[0*TXD+xi], w01 = s_w[1*TXD+xi];
            const float w10 = s_w[2*TXD+xi], w11 = s_w[3*TXD+xi];
            const int i00 = s_i[0*TXD+xi], i01 = s_i[1*TXD+xi];
            const int i10 = s_i[2*TXD+xi], i11 = s_i[3*TXD+xi];
            const float* p = xb + (size_t)c*HW;
            ob[(size_t)c*HW + xi] = w00*__ldg(p+i00) + w01*__ldg(p+i01)
                                  + w10*__ldg(p+i10) + w11*__ldg(p+i11);
        }
        return;
    }

    // ------------------ disparity path ------------------
    const int x0t = blockIdx.x * TXD;
    const int dg = t / 26;
    const int xg = t - dg*26;
    const bool act = (t < 312);

    const float* x1p = x1 + (size_t)b*CHW + (size_t)y*WW + x0t;
    const float* rp  = r1 + (size_t)b*CHW + (size_t)y*WW;

    float acc[16][4];
#pragma unroll
    for (int i = 0; i < 16; i++)
#pragma unroll
        for (int j = 0; j < 4; j++) acc[i][j] = 0.f;

    // ---- async tile loader (all-float4; boundary f4s are all-in or all-out)
    auto load_tile = [&](int bi, int kt) {
        float* da = sm + bi*DISP_BUF;
        float* dr = da + CTD*TXD;
        const int ct = kt * CTD;
#pragma unroll
        for (int i = t; i < CTD*26; i += 320) {
            int c = i / 26, x4 = (i - 26*c) * 4;
            __pipeline_memcpy_async(da + c*TXD + x4,
                                    x1p + (size_t)(ct+c)*HW + x4, 16);
        }
#pragma unroll
        for (int i = t; i < CTD*74; i += 320) {
            int c = i / 74, x4 = (i - 74*c) * 4;
            int gx = x0t - 96 + x4;
            float* dst = dr + c*RWD + x4;
            if ((unsigned)gx < WW)
                __pipeline_memcpy_async(dst, rp + (size_t)(ct+c)*HW + gx, 16);
            else
                *reinterpret_cast<float4*>(dst) = make_float4(0.f,0.f,0.f,0.f);
        }
    };

    load_tile(0, 0);
    __pipeline_commit();

    for (int k = 0; k < NTD; k++) {
        if (k + 1 < NTD) {
            load_tile((k+1) & 1, k+1);
            __pipeline_commit();
            __pipeline_wait_prior(1);
        } else {
            __pipeline_wait_prior(0);
        }
        __syncthreads();

        if (act) {
            const float* da = sm + (k&1)*DISP_BUF;
            const float* ap = da + xg*4;
            const float* bp = da + CTD*TXD + xg*4 + dg*16;
#pragma unroll 4
            for (int c = 0; c < CTD; c++) {
                const float4 a  = *reinterpret_cast<const float4*>(ap + c*TXD);
                const float4 q0 = *reinterpret_cast<const float4*>(bp + c*RWD);
                const float4 q1 = *reinterpret_cast<const float4*>(bp + c*RWD + 4);
                const float4 q2 = *reinterpret_cast<const float4*>(bp + c*RWD + 8);
                const float4 q3 = *reinterpret_cast<const float4*>(bp + c*RWD + 12);
                const float4 q4 = *reinterpret_cast<const float4*>(bp + c*RWD + 16);
                const float bv[20] = {q0.x,q0.y,q0.z,q0.w, q1.x,q1.y,q1.z,q1.w,
                                      q2.x,q2.y,q2.z,q2.w, q3.x,q3.y,q3.z,q3.w,
                                      q4.x,q4.y,q4.z,q4.w};
#pragma unroll
                for (int dj = 0; dj < 16; dj++) {
                    acc[dj][0] += a.x*bv[dj+0];
                    acc[dj][1] += a.y*bv[dj+1];
                    acc[dj][2] += a.z*bv[dj+2];
                    acc[dj][3] += a.w*bv[dj+3];
                }
            }
        }
        __syncthreads();
    }

    if (act) {
        float* op = out + ((size_t)(b*273 + 81 + dg*16)*HH + y)*WW + x0t + xg*4;
#pragma unroll
        for (int dj = 0; dj < 16; dj++) {
            float4 v;
            v.x = lrelu(acc[dj][0]);
            v.y = lrelu(acc[dj][1]);
            v.z = lrelu(acc[dj][2]);
            v.w = lrelu(acc[dj][3]);
            *reinterpret_cast<float4*>(op + (size_t)dj*HW) = v;
        }
    }
}

// ===========================================================================
// 81-channel cost volume  out[b, dy*9+dx, y, x] =
//   lrelu( sum_c x1[b,c,y,x] * x2w[b,c,y+dy-4,x+dx-4] ),  zero padded.
// (R7 config: FFMA + cp.async double buffer, (256,3) -> 3 blocks/SM)
// ===========================================================================
#define TXC 104
#define CTC 8
#define BWC 112                          // 104 + 8 halo
#define NTC (CC/CTC)                     // 8 pipeline stages
#define CORR_BUF (CTC*TXC + 9*CTC*BWC)   // 8896 floats per buffer
#define CORR_SMEM (2*CORR_BUF*4)         // 71168 B

__global__ __launch_bounds__(256, 3)
void corr_kernel(const float* __restrict__ x1, float* __restrict__ out) {
    extern __shared__ float sm[];

    const int x0t = blockIdx.x * TXC;
    const int y = blockIdx.y, b = blockIdx.z;
    const int t = threadIdx.x;
    const int dy = t / 26;
    const int xg = t - dy*26;
    const bool act = (t < 234);

    const float* x1p = x1 + (size_t)b*CHW + (size_t)y*WW + x0t;
    const float* wp  = g_x2w + (size_t)b*CHW;

    const int ca = t / 26, xa = (t - 26*ca) * 4;          // s_a: 208 f4, t<208
    const int cb = t / 28, xb4 = (t - 28*cb) * 4;         // s_b: 224 f4 per row
    const int gx2 = x0t - 4 + xb4;
    const bool px = ((unsigned)gx2 < WW);

    float acc[9][4];
#pragma unroll
    for (int i = 0; i < 9; i++)
#pragma unroll
        for (int j = 0; j < 4; j++) acc[i][j] = 0.f;

    auto load_tile = [&](int bi, int kt) {
        float* da = sm + bi*CORR_BUF;
        float* db = da + CTC*TXC;
        const int ct = kt * CTC;
        if (t < 208)
            __pipeline_memcpy_async(da + ca*TXC + xa,
                                    x1p + (size_t)(ct+ca)*HW + xa, 16);
        if (t < 224) {
            const float* srcb = wp + (size_t)(ct+cb)*HW + gx2;
            float* dstb = db + cb*BWC + xb4;
#pragma unroll
            for (int r = 0; r < 9; r++) {
                const int gy2 = y + r - 4;
                if (px && (unsigned)gy2 < HH)
                    __pipeline_memcpy_async(dstb + r*(CTC*BWC), srcb + gy2*WW, 16);
                else
                    *reinterpret_cast<float4*>(dstb + r*(CTC*BWC)) =
                        make_float4(0.f,0.f,0.f,0.f);
            }
        }
    };

    load_tile(0, 0);
    __pipeline_commit();

    for (int k = 0; k < NTC; k++) {
        if (k + 1 < NTC) {
            load_tile((k+1) & 1, k+1);
            __pipeline_commit();
            __pipeline_wait_prior(1);
        } else {
            __pipeline_wait_prior(0);
        }
        __syncthreads();

        if (act) {
            const float* da = sm + (k&1)*CORR_BUF;
            const float* ap = da + xg*4;
            const float* bp = da + CTC*TXC + dy*(CTC*BWC) + xg*4;
#pragma unroll
            for (int c = 0; c < CTC; c++) {
                const float4 a  = *reinterpret_cast<const float4*>(ap + c*TXC);
                const float4 q0 = *reinterpret_cast<const float4*>(bp + c*BWC);
                const float4 q1 = *reinterpret_cast<const float4*>(bp + c*BWC + 4);
                const float4 q2 = *reinterpret_cast<const float4*>(bp + c*BWC + 8);
                const float bv[12] = {q0.x,q0.y,q0.z,q0.w, q1.x,q1.y,q1.z,q1.w,
                                      q2.x,q2.y,q2.z,q2.w};
#pragma unroll
                for (int dx = 0; dx < 9; dx++) {
                    acc[dx][0] += a.x*bv[dx+0];
                    acc[dx][1] += a.y*bv[dx+1];
                    acc[dx][2] += a.z*bv[dx+2];
                    acc[dx][3] += a.w*bv[dx+3];
                }
            }
        }
        __syncthreads();
    }

    if (act) {
        float* op = out + ((size_t)(b*273 + dy*9)*HH + y)*WW + x0t + xg*4;
#pragma unroll
        for (int dx = 0; dx < 9; dx++) {
            float4 v;
            v.x = lrelu(acc[dx][0]);
            v.y = lrelu(acc[dx][1]);
            v.z = lrelu(acc[dx][2]);
            v.w = lrelu(acc[dx][3]);
            *reinterpret_cast<float4*>(op + (size_t)dx*HW) = v;
        }
    }
}

// ===========================================================================
extern "C" void kernel_launch(void* const* d_in, const int* in_sizes, int n_in,
                              void* d_out, int out_size) {
    const float* x1   = (const float*)d_in[0];
    const float* x2   = (const float*)d_in[1];
    const float* r1   = (const float*)d_in[2];
    const float* flow = (const float*)d_in[3];
    float* out = (float*)d_out;

    cudaFuncSetAttribute(fused_disp_warp, cudaFuncAttributeMaxDynamicSharedMemorySize, DSP_SMEM);
    cudaFuncSetAttribute(corr_kernel, cudaFuncAttributeMaxDynamicSharedMemorySize, CORR_SMEM);

    fused_disp_warp<<<dim3(8, HH, BB), 320, DSP_SMEM>>>(x1, r1, x2, flow, out);
    corr_kernel<<<dim3(WW/TXC, HH, BB), 256, CORR_SMEM>>>(x1, out);
}